// round 4
// baseline (speedup 1.0000x reference)
#include <cuda_runtime.h>
#include <math.h>

#define Bv 8
#define Tv 2048
#define Hv 1024
#define Mv (Bv*Tv)          // 16384 tokens
#define HOP 12
#define THRESH 0.9f
#define LN_EPS 1e-5f
#define H4 (Hv/4)           // 256

// ---- scratch (static device globals; no allocation) ----
__device__ float g_wt_t[Hv*Hv];        // Wt transposed: [h][o]
__device__ float g_c[HOP*Hv];          // c_k[o] = pos_k @ Wt^T + bt
__device__ float g_kc[64];             // 0..11 P1, 12..23 P2, 24..35 Pgw, 36 sum_gw, 37 bw
__device__ float g_alpha[Mv];
__device__ float g_gamma[Mv*HOP];

// =====================================================================
// K1: transpose Wt  (Wt[o][h] -> g_wt_t[h][o])
// =====================================================================
__global__ void k_transpose(const float* __restrict__ Wt) {
    __shared__ float tile[32][33];
    int x = blockIdx.x * 32 + threadIdx.x;
    int y = blockIdx.y * 32 + threadIdx.y;
    #pragma unroll
    for (int j = 0; j < 32; j += 8)
        tile[threadIdx.y + j][threadIdx.x] = Wt[(y + j) * Hv + x];
    __syncthreads();
    x = blockIdx.y * 32 + threadIdx.x;
    y = blockIdx.x * 32 + threadIdx.y;
    #pragma unroll
    for (int j = 0; j < 32; j += 8)
        g_wt_t[(y + j) * Hv + x] = tile[threadIdx.x][threadIdx.y + j];
}

// =====================================================================
// K2: c_k[o] = sum_h pos_k[h] * Wt[o][h] + bt[o].  One warp per (k,o).
// grid (12, 128), block 256 (8 warps)
// =====================================================================
__global__ void k_cvec(const float* __restrict__ pos,
                       const float* __restrict__ Wt,
                       const float* __restrict__ bt) {
    int k = blockIdx.x;
    int warp = threadIdx.x >> 5, lane = threadIdx.x & 31;
    int o = blockIdx.y * 8 + warp;
    const float* pr = pos + k * Hv;
    const float* wr = Wt + o * Hv;
    float acc = 0.0f;
    #pragma unroll 8
    for (int i = lane; i < Hv; i += 32) acc += pr[i] * wr[i];
    #pragma unroll
    for (int s = 16; s; s >>= 1) acc += __shfl_xor_sync(0xffffffffu, acc, s);
    if (lane == 0) g_c[k * Hv + o] = acc + bt[o];
}

// =====================================================================
// K3: per-hop scalar constants. 1 block, 256 threads.
//   P1_k = sum pos_k, P2_k = sum pos_k^2, Pgw_k = sum pos_k*(gamma*w_p)
//   sum_gw = sum gamma*w_p, bw = sum beta*w_p
// =====================================================================
__global__ void k_scal(const float* __restrict__ pos,
                       const float* __restrict__ gamma,
                       const float* __restrict__ beta,
                       const float* __restrict__ wp) {
    int tid = threadIdx.x;
    float vals[38];
    #pragma unroll
    for (int q = 0; q < 38; q++) vals[q] = 0.0f;
    for (int h = tid; h < Hv; h += 256) {
        float w  = wp[h];
        float gw = gamma[h] * w;
        vals[36] += gw;
        vals[37] += beta[h] * w;
        #pragma unroll
        for (int k = 0; k < HOP; k++) {
            float v = pos[k * Hv + h];
            vals[k]      += v;
            vals[12 + k] += v * v;
            vals[24 + k] += v * gw;
        }
    }
    __shared__ float red[256];
    for (int q = 0; q < 38; q++) {
        red[tid] = vals[q];
        __syncthreads();
        for (int s = 128; s; s >>= 1) {
            if (tid < s) red[tid] += red[tid + s];
            __syncthreads();
        }
        if (tid == 0) g_kc[q] = red[0];
        __syncthreads();
    }
}

// =====================================================================
// K4: per-token stats + scalar ACT loop.
// grid 2048 blocks x 256 threads; warp w handles token m = blk*8 + w.
// Shared: pos_enc (48KB exactly).
// Writes g_alpha, g_gamma, and rem / n_up outputs.
// =====================================================================
__global__ __launch_bounds__(256) void k_token(
    const float* __restrict__ inp, const float* __restrict__ tenc,
    const float* __restrict__ pos, const float* __restrict__ gamma,
    const float* __restrict__ wp, const float* __restrict__ bp,
    float* __restrict__ out)
{
    __shared__ float4 s_pos[HOP * H4];   // 12*256 float4 = 48KB
    int tid = threadIdx.x;
    for (int i = tid; i < HOP * H4; i += 256)
        s_pos[i] = ((const float4*)pos)[i];
    __syncthreads();

    int warp = tid >> 5, lane = tid & 31;
    int m = blockIdx.x * 8 + warp;
    int t = m & (Tv - 1);

    const float4* ip = (const float4*)inp + (size_t)m * H4;
    const float4* tp = (const float4*)tenc + (size_t)t * H4;
    const float4* gp = (const float4*)gamma;
    const float4* wpp = (const float4*)wp;

    float S1 = 0.0f, S2 = 0.0f, A = 0.0f, D[HOP];
    #pragma unroll
    for (int k = 0; k < HOP; k++) D[k] = 0.0f;

    #pragma unroll
    for (int i = 0; i < H4 / 32; i++) {           // 8 iters
        int h4 = lane + 32 * i;
        float4 a = ip[h4], b = tp[h4];
        float4 x = make_float4(a.x + b.x, a.y + b.y, a.z + b.z, a.w + b.w);
        float4 g = gp[h4], w = wpp[h4];
        S1 += x.x + x.y + x.z + x.w;
        S2 += x.x * x.x + x.y * x.y + x.z * x.z + x.w * x.w;
        A  += x.x * (g.x * w.x) + x.y * (g.y * w.y)
            + x.z * (g.z * w.z) + x.w * (g.w * w.w);
        #pragma unroll
        for (int k = 0; k < HOP; k++) {
            float4 pv = s_pos[k * H4 + h4];
            D[k] += x.x * pv.x + x.y * pv.y + x.z * pv.z + x.w * pv.w;
        }
    }
    #pragma unroll
    for (int s = 16; s; s >>= 1) {
        S1 += __shfl_xor_sync(0xffffffffu, S1, s);
        S2 += __shfl_xor_sync(0xffffffffu, S2, s);
        A  += __shfl_xor_sync(0xffffffffu, A,  s);
        #pragma unroll
        for (int k = 0; k < HOP; k++)
            D[k] += __shfl_xor_sync(0xffffffffu, D[k], s);
    }

    if (lane == 0) {
        float sgw = g_kc[36], bw = g_kc[37], bpv = bp[0];
        float hp = 0.0f, rem = 0.0f, nup = 0.0f;
        float uw[HOP];
        #pragma unroll
        for (int k = 0; k < HOP; k++) {
            float mu  = (S1 + g_kc[k]) * (1.0f / Hv);
            float e2  = (S2 + 2.0f * D[k] + g_kc[12 + k]) * (1.0f / Hv);
            float var = e2 - mu * mu;
            float inv = 1.0f / sqrtf(var + LN_EPS);
            float logit = inv * (A + g_kc[24 + k] - mu * sgw) + bw + bpv;
            float p = 1.0f / (1.0f + expf(-logit));
            float sr = (hp < 1.0f) ? 1.0f : 0.0f;
            float acc = hp + p * sr;
            float nh  = (acc > THRESH)  ? sr : 0.0f;
            sr        = (acc <= THRESH) ? sr : 0.0f;
            hp  += p * sr;
            rem += nh * (1.0f - hp);
            hp  += nh * rem;
            nup += sr + nh;
            uw[k] = p * sr + nh * rem;
        }
        // gamma_k = uw_k * prod_{j>k}(1-uw_j); alpha = sum gamma_k
        float suf = 1.0f, alpha = 0.0f;
        #pragma unroll
        for (int k = HOP - 1; k >= 0; k--) {
            float gk = uw[k] * suf;
            g_gamma[m * HOP + k] = gk;
            alpha += gk;
            suf *= (1.0f - uw[k]);
        }
        g_alpha[m] = alpha;
        out[(size_t)Mv * Hv + m]      = rem;   // rem output
        out[(size_t)Mv * Hv + Mv + m] = nup;   // n_updates output
    }
}

// =====================================================================
// K5: GEMM + epilogue.
//   out[m][o] = alpha[m] * (base[m,:] . WtT[:,o]) + sum_k gamma[m][k]*c_k[o]
// base computed on the fly = inputs + time_enc.
// BM=BN=128, BK=8, 256 threads, 8x8 per thread.
// =====================================================================
#define BM 128
#define BN 128
#define BK 8

__global__ __launch_bounds__(256, 2) void k_gemm(
    const float* __restrict__ inp, const float* __restrict__ tenc,
    float* __restrict__ out)
{
    __shared__ float As[BK][BM];
    __shared__ float Bs[BK][BN];
    __shared__ float sC[HOP][BN];
    __shared__ float sG[BM * HOP];
    __shared__ float sAl[BM];

    int tid = threadIdx.x;
    int n0 = blockIdx.x * BN;
    int m0 = blockIdx.y * BM;

    // epilogue data
    for (int i = tid; i < HOP * (BN / 4); i += 256) {
        int k = i / (BN / 4), c4 = i % (BN / 4);
        ((float4*)&sC[k][0])[c4] = ((const float4*)&g_c[k * Hv + n0])[c4];
    }
    for (int i = tid; i < BM * HOP / 4; i += 256)
        ((float4*)sG)[i] = ((const float4*)&g_gamma[m0 * HOP])[i];
    if (tid < BM) sAl[tid] = g_alpha[m0 + tid];

    float acc[8][8];
    #pragma unroll
    for (int i = 0; i < 8; i++)
        #pragma unroll
        for (int j = 0; j < 8; j++) acc[i][j] = 0.0f;

    int tx = tid & 15, ty = tid >> 4;

    int ar = tid >> 1, ac4 = tid & 1;         // A tile: row, which float4 of 8 k's
    int am = m0 + ar;
    int at = am & (Tv - 1);
    const float4* Ai = (const float4*)inp + (size_t)am * H4;
    const float4* At = (const float4*)tenc + (size_t)at * H4;
    int bkr = tid >> 5, bc4 = tid & 31;       // B tile: k-row, which float4 of 128 n's

    for (int kt = 0; kt < Hv / BK; kt++) {
        float4 a  = Ai[kt * 2 + ac4];
        float4 t4 = At[kt * 2 + ac4];
        float4 b4 = ((const float4*)&g_wt_t[(size_t)(kt * BK + bkr) * Hv + n0])[bc4];
        As[ac4 * 4 + 0][ar] = a.x + t4.x;
        As[ac4 * 4 + 1][ar] = a.y + t4.y;
        As[ac4 * 4 + 2][ar] = a.z + t4.z;
        As[ac4 * 4 + 3][ar] = a.w + t4.w;
        ((float4*)&Bs[bkr][0])[bc4] = b4;
        __syncthreads();
        #pragma unroll
        for (int k = 0; k < BK; k++) {
            float ra[8], rb[8];
            #pragma unroll
            for (int i = 0; i < 8; i++) ra[i] = As[k][ty * 8 + i];
            #pragma unroll
            for (int j = 0; j < 8; j++) rb[j] = Bs[k][tx * 8 + j];
            #pragma unroll
            for (int i = 0; i < 8; i++)
                #pragma unroll
                for (int j = 0; j < 8; j++)
                    acc[i][j] += ra[i] * rb[j];
        }
        __syncthreads();
    }

    // epilogue: out = alpha*acc + sum_k gamma_k * c_k
    #pragma unroll
    for (int i = 0; i < 8; i++) {
        int r = ty * 8 + i;
        float al = sAl[r];
        float e[8];
        #pragma unroll
        for (int j = 0; j < 8; j++) e[j] = 0.0f;
        #pragma unroll
        for (int k = 0; k < HOP; k++) {
            float gk = sG[r * HOP + k];
            #pragma unroll
            for (int j = 0; j < 8; j++) e[j] += gk * sC[k][tx * 8 + j];
        }
        float* orow = out + (size_t)(m0 + r) * Hv + n0 + tx * 8;
        float4 o0 = make_float4(al * acc[i][0] + e[0], al * acc[i][1] + e[1],
                                al * acc[i][2] + e[2], al * acc[i][3] + e[3]);
        float4 o1 = make_float4(al * acc[i][4] + e[4], al * acc[i][5] + e[5],
                                al * acc[i][6] + e[6], al * acc[i][7] + e[7]);
        ((float4*)orow)[0] = o0;
        ((float4*)orow)[1] = o1;
    }
}

// =====================================================================
extern "C" void kernel_launch(void* const* d_in, const int* in_sizes, int n_in,
                              void* d_out, int out_size) {
    const float* inputs  = (const float*)d_in[0];   // [8,2048,1024]
    const float* time_e  = (const float*)d_in[1];   // [1,2048,1024]
    const float* pos_e   = (const float*)d_in[2];   // [1,12,1024]
    const float* ln_g    = (const float*)d_in[3];   // [1024]
    const float* ln_b    = (const float*)d_in[4];   // [1024]
    const float* w_p     = (const float*)d_in[5];   // [1024]
    const float* b_p     = (const float*)d_in[6];   // [1]
    const float* Wt      = (const float*)d_in[7];   // [1024,1024]
    const float* bt      = (const float*)d_in[8];   // [1024]
    float* out = (float*)d_out;

    k_transpose<<<dim3(32, 32), dim3(32, 8)>>>(Wt);
    k_cvec<<<dim3(HOP, 128), 256>>>(pos_e, Wt, bt);
    k_scal<<<1, 256>>>(pos_e, ln_g, ln_b, w_p);
    k_token<<<Mv / 8, 256>>>(inputs, time_e, pos_e, ln_g, w_p, b_p, out);
    k_gemm<<<dim3(Hv / BN, Mv / BM), 256>>>(inputs, time_e, out);
}

// round 5
// speedup vs baseline: 2.5305x; 2.5305x over previous
#include <cuda_runtime.h>
#include <math.h>
#include <stdint.h>

#define Bv 8
#define Tv 2048
#define Hv 1024
#define Mv (Bv*Tv)          // 16384 tokens
#define HOP 12
#define THRESH 0.9f
#define LN_EPS 1e-5f
#define H4 (Hv/4)           // 256

// ---- scratch (static device globals; no allocation) ----
__device__ float g_wt_t[Hv*Hv];        // Wt transposed: [h][o]
__device__ float g_c[HOP*Hv];          // c_k[o] = pos_k @ Wt^T + bt
__device__ float g_kc[64];             // 0..11 P1, 12..23 P2, 24..35 Pgw, 36 sum_gw, 37 bw
__device__ float g_alpha[Mv];
__device__ float g_gamma[Mv*HOP];

// =====================================================================
// K1: transpose Wt  (Wt[o][h] -> g_wt_t[h][o])
// =====================================================================
__global__ void k_transpose(const float* __restrict__ Wt) {
    __shared__ float tile[32][33];
    int x = blockIdx.x * 32 + threadIdx.x;
    int y = blockIdx.y * 32 + threadIdx.y;
    #pragma unroll
    for (int j = 0; j < 32; j += 8)
        tile[threadIdx.y + j][threadIdx.x] = Wt[(y + j) * Hv + x];
    __syncthreads();
    x = blockIdx.y * 32 + threadIdx.x;
    y = blockIdx.x * 32 + threadIdx.y;
    #pragma unroll
    for (int j = 0; j < 32; j += 8)
        g_wt_t[(y + j) * Hv + x] = tile[threadIdx.x][threadIdx.y + j];
}

// =====================================================================
// K2: c_k[o] = sum_h pos_k[h] * Wt[o][h] + bt[o].  One warp per (k,o).
// =====================================================================
__global__ void k_cvec(const float* __restrict__ pos,
                       const float* __restrict__ Wt,
                       const float* __restrict__ bt) {
    int k = blockIdx.x;
    int warp = threadIdx.x >> 5, lane = threadIdx.x & 31;
    int o = blockIdx.y * 8 + warp;
    const float* pr = pos + k * Hv;
    const float* wr = Wt + o * Hv;
    float acc = 0.0f;
    #pragma unroll 8
    for (int i = lane; i < Hv; i += 32) acc += pr[i] * wr[i];
    #pragma unroll
    for (int s = 16; s; s >>= 1) acc += __shfl_xor_sync(0xffffffffu, acc, s);
    if (lane == 0) g_c[k * Hv + o] = acc + bt[o];
}

// =====================================================================
// K3: per-hop scalar constants. 1 block, 256 threads.
// =====================================================================
__global__ void k_scal(const float* __restrict__ pos,
                       const float* __restrict__ gamma,
                       const float* __restrict__ beta,
                       const float* __restrict__ wp) {
    int tid = threadIdx.x;
    float vals[38];
    #pragma unroll
    for (int q = 0; q < 38; q++) vals[q] = 0.0f;
    for (int h = tid; h < Hv; h += 256) {
        float w  = wp[h];
        float gw = gamma[h] * w;
        vals[36] += gw;
        vals[37] += beta[h] * w;
        #pragma unroll
        for (int k = 0; k < HOP; k++) {
            float v = pos[k * Hv + h];
            vals[k]      += v;
            vals[12 + k] += v * v;
            vals[24 + k] += v * gw;
        }
    }
    __shared__ float red[256];
    for (int q = 0; q < 38; q++) {
        red[tid] = vals[q];
        __syncthreads();
        for (int s = 128; s; s >>= 1) {
            if (tid < s) red[tid] += red[tid + s];
            __syncthreads();
        }
        if (tid == 0) g_kc[q] = red[0];
        __syncthreads();
    }
}

// =====================================================================
// K4: per-token stats + scalar ACT loop (unchanged; 68us)
// =====================================================================
__global__ __launch_bounds__(256) void k_token(
    const float* __restrict__ inp, const float* __restrict__ tenc,
    const float* __restrict__ pos, const float* __restrict__ gamma,
    const float* __restrict__ wp, const float* __restrict__ bp,
    float* __restrict__ out)
{
    __shared__ float4 s_pos[HOP * H4];   // 48KB
    int tid = threadIdx.x;
    for (int i = tid; i < HOP * H4; i += 256)
        s_pos[i] = ((const float4*)pos)[i];
    __syncthreads();

    int warp = tid >> 5, lane = tid & 31;
    int m = blockIdx.x * 8 + warp;
    int t = m & (Tv - 1);

    const float4* ip = (const float4*)inp + (size_t)m * H4;
    const float4* tp = (const float4*)tenc + (size_t)t * H4;
    const float4* gp = (const float4*)gamma;
    const float4* wpp = (const float4*)wp;

    float S1 = 0.0f, S2 = 0.0f, A = 0.0f, D[HOP];
    #pragma unroll
    for (int k = 0; k < HOP; k++) D[k] = 0.0f;

    #pragma unroll
    for (int i = 0; i < H4 / 32; i++) {
        int h4 = lane + 32 * i;
        float4 a = ip[h4], b = tp[h4];
        float4 x = make_float4(a.x + b.x, a.y + b.y, a.z + b.z, a.w + b.w);
        float4 g = gp[h4], w = wpp[h4];
        S1 += x.x + x.y + x.z + x.w;
        S2 += x.x * x.x + x.y * x.y + x.z * x.z + x.w * x.w;
        A  += x.x * (g.x * w.x) + x.y * (g.y * w.y)
            + x.z * (g.z * w.z) + x.w * (g.w * w.w);
        #pragma unroll
        for (int k = 0; k < HOP; k++) {
            float4 pv = s_pos[k * H4 + h4];
            D[k] += x.x * pv.x + x.y * pv.y + x.z * pv.z + x.w * pv.w;
        }
    }
    #pragma unroll
    for (int s = 16; s; s >>= 1) {
        S1 += __shfl_xor_sync(0xffffffffu, S1, s);
        S2 += __shfl_xor_sync(0xffffffffu, S2, s);
        A  += __shfl_xor_sync(0xffffffffu, A,  s);
        #pragma unroll
        for (int k = 0; k < HOP; k++)
            D[k] += __shfl_xor_sync(0xffffffffu, D[k], s);
    }

    if (lane == 0) {
        float sgw = g_kc[36], bw = g_kc[37], bpv = bp[0];
        float hp = 0.0f, rem = 0.0f, nup = 0.0f;
        float uw[HOP];
        #pragma unroll
        for (int k = 0; k < HOP; k++) {
            float mu  = (S1 + g_kc[k]) * (1.0f / Hv);
            float e2  = (S2 + 2.0f * D[k] + g_kc[12 + k]) * (1.0f / Hv);
            float var = e2 - mu * mu;
            float inv = 1.0f / sqrtf(var + LN_EPS);
            float logit = inv * (A + g_kc[24 + k] - mu * sgw) + bw + bpv;
            float p = 1.0f / (1.0f + expf(-logit));
            float sr = (hp < 1.0f) ? 1.0f : 0.0f;
            float acc = hp + p * sr;
            float nh  = (acc > THRESH)  ? sr : 0.0f;
            sr        = (acc <= THRESH) ? sr : 0.0f;
            hp  += p * sr;
            rem += nh * (1.0f - hp);
            hp  += nh * rem;
            nup += sr + nh;
            uw[k] = p * sr + nh * rem;
        }
        float suf = 1.0f, alpha = 0.0f;
        #pragma unroll
        for (int k = HOP - 1; k >= 0; k--) {
            float gk = uw[k] * suf;
            g_gamma[m * HOP + k] = gk;
            alpha += gk;
            suf *= (1.0f - uw[k]);
        }
        g_alpha[m] = alpha;
        out[(size_t)Mv * Hv + m]      = rem;
        out[(size_t)Mv * Hv + Mv + m] = nup;
    }
}

// =====================================================================
// K5: TF32 tensor-core GEMM + epilogue.
//   out[m][o] = alpha[m]*(base[m,:].WtT[:,o]) + sum_k gamma[m][k]*c_k[o]
// BM=BN=128, BK=16; 8 warps (2M x 4N), warp tile 64x32, mma m16n8k8.
// k-permutation: fragment col f <-> phys k = 8*s + 2*(f&3) + (f>>2),
// applied to BOTH A and B, so A fragments load as one LDS.64 per pair.
// =====================================================================
#define BM 128
#define BN 128
#define BK 16
#define KT (Hv/BK)    // 64

__device__ __forceinline__ uint32_t f2tf(float f) {
    uint32_t u;
    asm("cvt.rna.tf32.f32 %0, %1;" : "=r"(u) : "f"(f));
    return u;
}

__device__ __forceinline__ void mma_tf32(float c[4], uint32_t a0, uint32_t a1,
                                         uint32_t a2, uint32_t a3,
                                         uint32_t b0, uint32_t b1) {
    asm volatile(
        "mma.sync.aligned.m16n8k8.row.col.f32.tf32.tf32.f32 "
        "{%0,%1,%2,%3}, {%4,%5,%6,%7}, {%8,%9}, {%0,%1,%2,%3};"
        : "+f"(c[0]), "+f"(c[1]), "+f"(c[2]), "+f"(c[3])
        : "r"(a0), "r"(a1), "r"(a2), "r"(a3), "r"(b0), "r"(b1));
}

__global__ __launch_bounds__(256, 2) void k_gemm_tc(
    const float* __restrict__ inp, const float* __restrict__ tenc,
    float* __restrict__ out)
{
    // A tile, k-pair interleaved: AsV[buf][pair p][m] = (A[m][2p], A[m][2p+1]) as tf32
    __shared__ uint2    AsV[2][8][132];    // 16896 B
    __shared__ uint32_t Bs[2][BK][140];    // 17920 B (140*4=560, 16B-aligned rows)
    __shared__ float    sC[HOP][BN];       // 6144 B
    __shared__ float    sG[BM * HOP];      // 6144 B
    __shared__ float    sAl[BM];           // 512 B

    int tid  = threadIdx.x;
    int lane = tid & 31, wid = tid >> 5;
    int tig  = lane & 3, lrow = lane >> 2;       // fragment group indices
    int warp_m = wid & 1, warp_n = wid >> 1;
    int n0 = blockIdx.x * BN;
    int m0 = blockIdx.y * BM;

    // ---- epilogue data into smem ----
    for (int i = tid; i < HOP * (BN / 4); i += 256) {
        int k = i >> 5, c4 = i & 31;
        ((float4*)&sC[k][0])[c4] = ((const float4*)&g_c[k * Hv + n0])[c4];
    }
    for (int i = tid; i < BM * HOP / 4; i += 256)
        ((float4*)sG)[i] = ((const float4*)&g_gamma[(size_t)m0 * HOP])[i];
    if (tid < BM) sAl[tid] = g_alpha[m0 + tid];

    // ---- global-load indexing ----
    // A: 128 rows x 4 float4 of k. idx = tid, tid+256 -> row=idx>>2, c4=idx&3
    int arow0 = tid >> 2, ac4 = tid & 3;
    int am0 = m0 + arow0, am1 = m0 + arow0 + 64;
    int at0 = am0 & (Tv - 1), at1 = am1 & (Tv - 1);
    // B: 16 rows x 32 float4 of n. idx -> krow=idx>>5, c4=idx&31
    int bkr = tid >> 5, bc4 = tid & 31;

    float acc[4][4][4];
    #pragma unroll
    for (int i = 0; i < 4; i++)
        #pragma unroll
        for (int j = 0; j < 4; j++)
            #pragma unroll
            for (int r = 0; r < 4; r++) acc[i][j][r] = 0.0f;

    // prefetch registers (tf32-converted)
    uint32_t pa[2][4];   // two A float4 (row, row+64), summed+converted
    uint32_t pb[2][4];   // two B float4 (krow, krow+8)

    auto gload = [&](int kt) {
        const float4* Ai0 = (const float4*)(inp  + (size_t)am0 * Hv) + kt * 4 + ac4;
        const float4* At0 = (const float4*)(tenc + (size_t)at0 * Hv) + kt * 4 + ac4;
        const float4* Ai1 = (const float4*)(inp  + (size_t)am1 * Hv) + kt * 4 + ac4;
        const float4* At1 = (const float4*)(tenc + (size_t)at1 * Hv) + kt * 4 + ac4;
        float4 a0 = *Ai0, t0 = *At0, a1 = *Ai1, t1 = *At1;
        pa[0][0] = f2tf(a0.x + t0.x); pa[0][1] = f2tf(a0.y + t0.y);
        pa[0][2] = f2tf(a0.z + t0.z); pa[0][3] = f2tf(a0.w + t0.w);
        pa[1][0] = f2tf(a1.x + t1.x); pa[1][1] = f2tf(a1.y + t1.y);
        pa[1][2] = f2tf(a1.z + t1.z); pa[1][3] = f2tf(a1.w + t1.w);
        float4 b0 = ((const float4*)&g_wt_t[(size_t)(kt * BK + bkr) * Hv + n0])[bc4];
        float4 b1 = ((const float4*)&g_wt_t[(size_t)(kt * BK + bkr + 8) * Hv + n0])[bc4];
        pb[0][0] = f2tf(b0.x); pb[0][1] = f2tf(b0.y);
        pb[0][2] = f2tf(b0.z); pb[0][3] = f2tf(b0.w);
        pb[1][0] = f2tf(b1.x); pb[1][1] = f2tf(b1.y);
        pb[1][2] = f2tf(b1.z); pb[1][3] = f2tf(b1.w);
    };
    auto sstore = [&](int buf) {
        // A: float4 covers phys k 4c4..4c4+3 -> pairs 2c4 (k0,k1), 2c4+1 (k2,k3)
        AsV[buf][2 * ac4    ][arow0]      = make_uint2(pa[0][0], pa[0][1]);
        AsV[buf][2 * ac4 + 1][arow0]      = make_uint2(pa[0][2], pa[0][3]);
        AsV[buf][2 * ac4    ][arow0 + 64] = make_uint2(pa[1][0], pa[1][1]);
        AsV[buf][2 * ac4 + 1][arow0 + 64] = make_uint2(pa[1][2], pa[1][3]);
        *(uint4*)&Bs[buf][bkr    ][bc4 * 4] = make_uint4(pb[0][0], pb[0][1], pb[0][2], pb[0][3]);
        *(uint4*)&Bs[buf][bkr + 8][bc4 * 4] = make_uint4(pb[1][0], pb[1][1], pb[1][2], pb[1][3]);
    };

    gload(0);
    sstore(0);
    __syncthreads();

    for (int kt = 0; kt < KT; kt++) {
        int buf = kt & 1;
        int ktn = (kt + 1 < KT) ? kt + 1 : KT - 1;
        gload(ktn);

        #pragma unroll
        for (int s = 0; s < 2; s++) {
            uint32_t af[4][4];  // [mtile][a0..a3]
            #pragma unroll
            for (int i = 0; i < 4; i++) {
                int row0 = warp_m * 64 + i * 16 + lrow;
                uint2 lo = AsV[buf][s * 4 + tig][row0];       // (a0, a2)
                uint2 hi = AsV[buf][s * 4 + tig][row0 + 8];   // (a1, a3)
                af[i][0] = lo.x; af[i][1] = hi.x; af[i][2] = lo.y; af[i][3] = hi.y;
            }
            uint32_t bf[4][2];  // [ntile][b0,b1]
            #pragma unroll
            for (int j = 0; j < 4; j++) {
                int coln = warp_n * 32 + j * 8 + lrow;
                bf[j][0] = Bs[buf][s * 8 + 2 * tig    ][coln];
                bf[j][1] = Bs[buf][s * 8 + 2 * tig + 1][coln];
            }
            #pragma unroll
            for (int i = 0; i < 4; i++)
                #pragma unroll
                for (int j = 0; j < 4; j++)
                    mma_tf32(acc[i][j], af[i][0], af[i][1], af[i][2], af[i][3],
                             bf[j][0], bf[j][1]);
        }

        sstore(buf ^ 1);
        __syncthreads();
    }

    // ---- epilogue: out = alpha*acc + sum_k gamma_k * c_k ----
    #pragma unroll
    for (int i = 0; i < 4; i++) {
        #pragma unroll
        for (int h = 0; h < 2; h++) {
            int lr = warp_m * 64 + i * 16 + h * 8 + lrow;   // block-local row
            float al = sAl[lr];
            const float* grow = &sG[lr * HOP];
            #pragma unroll
            for (int j = 0; j < 4; j++) {
                int cb = warp_n * 32 + j * 8 + 2 * tig;     // block-local col (even)
                float ex = 0.0f, ey = 0.0f;
                #pragma unroll
                for (int k = 0; k < HOP; k++) {
                    float gk = grow[k];
                    float2 cp = *(const float2*)&sC[k][cb];
                    ex += gk * cp.x;
                    ey += gk * cp.y;
                }
                float2 o;
                o.x = al * acc[i][j][2 * h + 0] + ex;
                o.y = al * acc[i][j][2 * h + 1] + ey;
                *(float2*)&out[(size_t)(m0 + lr) * Hv + n0 + cb] = o;
            }
        }
    }
}

// =====================================================================
extern "C" void kernel_launch(void* const* d_in, const int* in_sizes, int n_in,
                              void* d_out, int out_size) {
    const float* inputs  = (const float*)d_in[0];   // [8,2048,1024]
    const float* time_e  = (const float*)d_in[1];   // [1,2048,1024]
    const float* pos_e   = (const float*)d_in[2];   // [1,12,1024]
    const float* ln_g    = (const float*)d_in[3];   // [1024]
    const float* ln_b    = (const float*)d_in[4];   // [1024]
    const float* w_p     = (const float*)d_in[5];   // [1024]
    const float* b_p     = (const float*)d_in[6];   // [1]
    const float* Wt      = (const float*)d_in[7];   // [1024,1024]
    const float* bt      = (const float*)d_in[8];   // [1024]
    float* out = (float*)d_out;

    k_transpose<<<dim3(32, 32), dim3(32, 8)>>>(Wt);
    k_cvec<<<dim3(HOP, 128), 256>>>(pos_e, Wt, bt);
    k_scal<<<1, 256>>>(pos_e, ln_g, ln_b, w_p);
    k_token<<<Mv / 8, 256>>>(inputs, time_e, pos_e, ln_g, w_p, b_p, out);
    k_gemm_tc<<<dim3(Hv / BN, Mv / BM), 256>>>(inputs, time_e, out);
}

// round 7
// speedup vs baseline: 3.9511x; 1.5614x over previous
#include <cuda_runtime.h>
#include <math.h>
#include <stdint.h>

#define Bv 8
#define Tv 2048
#define Hv 1024
#define Mv (Bv*Tv)          // 16384 tokens
#define HOP 12
#define THRESH 0.9f
#define LN_EPS 1e-5f
#define H4 (Hv/4)           // 256

// ---- scratch (static device globals; no allocation) ----
__device__ float g_wtr[Hv*Hv];          // Wt, tf32-rounded, [o][k]
__device__ float g_basep[(size_t)Mv*Hv];// base, tf32-rounded, uint4-interleaved
__device__ float g_c[HOP*Hv];           // c_k[o] = pos_k @ Wt^T + bt  (exact)
__device__ float g_kc[64];              // 0..11 P1, 12..23 P2, 24..35 Pgw, 36 sgw, 37 bw
__device__ float g_alpha[Mv];
__device__ float g_gamma[Mv*HOP];

// ======================= PTX helpers =================================
__device__ __forceinline__ uint32_t f2tf(float f) {
    uint32_t u;
    asm("cvt.rna.tf32.f32 %0, %1;" : "=r"(u) : "f"(f));
    return u;
}
__device__ __forceinline__ uint32_t smem_u32(const void* p) {
    uint32_t a;
    asm("{ .reg .u64 t; cvta.to.shared.u64 t, %1; cvt.u32.u64 %0, t; }"
        : "=r"(a) : "l"(p));
    return a;
}
__device__ __forceinline__ void cpasync16(uint32_t dst, const void* src) {
    asm volatile("cp.async.cg.shared.global [%0], [%1], 16;" :: "r"(dst), "l"(src));
}
#define CP_COMMIT() asm volatile("cp.async.commit_group;" ::: "memory")
#define CP_WAIT(n)  asm volatile("cp.async.wait_group %0;" :: "n"(n) : "memory")

__device__ __forceinline__ void mma_tf32(float c[4], uint32_t a0, uint32_t a1,
                                         uint32_t a2, uint32_t a3,
                                         uint32_t b0, uint32_t b1) {
    asm volatile(
        "mma.sync.aligned.m16n8k8.row.col.f32.tf32.tf32.f32 "
        "{%0,%1,%2,%3}, {%4,%5,%6,%7}, {%8,%9}, {%0,%1,%2,%3};"
        : "+f"(c[0]), "+f"(c[1]), "+f"(c[2]), "+f"(c[3])
        : "r"(a0), "r"(a1), "r"(a2), "r"(a3), "r"(b0), "r"(b1));
}

// =====================================================================
// K1: per-hop scalar constants. 1 block, 256 threads.
// =====================================================================
__global__ void k_scal(const float* __restrict__ pos,
                       const float* __restrict__ gamma,
                       const float* __restrict__ beta,
                       const float* __restrict__ wp) {
    int tid = threadIdx.x;
    float vals[38];
    #pragma unroll
    for (int q = 0; q < 38; q++) vals[q] = 0.0f;
    for (int h = tid; h < Hv; h += 256) {
        float w  = wp[h];
        float gw = gamma[h] * w;
        vals[36] += gw;
        vals[37] += beta[h] * w;
        #pragma unroll
        for (int k = 0; k < HOP; k++) {
            float v = pos[k * Hv + h];
            vals[k]      += v;
            vals[12 + k] += v * v;
            vals[24 + k] += v * gw;
        }
    }
    __shared__ float red[256];
    for (int q = 0; q < 38; q++) {
        red[tid] = vals[q];
        __syncthreads();
        for (int s = 128; s; s >>= 1) {
            if (tid < s) red[tid] += red[tid + s];
            __syncthreads();
        }
        if (tid == 0) g_kc[q] = red[0];
        __syncthreads();
    }
}

// =====================================================================
// K2: per-token stats + scalar ACT loop.  Writes g_basep (tf32-rounded
// base in uint4-fragment interleave) for the GEMM:
//   uint4 at (j, kp) = (E[2kp], O[2kp], E[2kp+1], O[2kp+1]),
//   E = token 2j, O = token 2j+1.
// =====================================================================
__global__ __launch_bounds__(256) void k_token(
    const float* __restrict__ inp, const float* __restrict__ tenc,
    const float* __restrict__ pos, const float* __restrict__ gamma,
    const float* __restrict__ wp, const float* __restrict__ bp,
    float* __restrict__ out)
{
    __shared__ float4 s_pos[HOP * H4];   // 48KB
    int tid = threadIdx.x;
    for (int i = tid; i < HOP * H4; i += 256)
        s_pos[i] = ((const float4*)pos)[i];
    __syncthreads();

    int warp = tid >> 5, lane = tid & 31;
    int m = blockIdx.x * 8 + warp;
    int t = m & (Tv - 1);
    int jp = m >> 1, half = m & 1;

    const float4* ip = (const float4*)inp + (size_t)m * H4;
    const float4* tp = (const float4*)tenc + (size_t)t * H4;
    const float4* gp = (const float4*)gamma;
    const float4* wpp = (const float4*)wp;

    float S1 = 0.0f, S2 = 0.0f, A = 0.0f, D[HOP];
    #pragma unroll
    for (int k = 0; k < HOP; k++) D[k] = 0.0f;

    #pragma unroll
    for (int i = 0; i < H4 / 32; i++) {
        int h4 = lane + 32 * i;
        float4 a = ip[h4], b = tp[h4];
        float4 x = make_float4(a.x + b.x, a.y + b.y, a.z + b.z, a.w + b.w);
        // packed tf32 store: words (jp*512 + 2*h4)*4 + half + {0,2,4,6}
        {
            size_t wb = ((size_t)jp * 512 + 2 * h4) * 4 + half;
            g_basep[wb]     = __uint_as_float(f2tf(x.x));
            g_basep[wb + 2] = __uint_as_float(f2tf(x.y));
            g_basep[wb + 4] = __uint_as_float(f2tf(x.z));
            g_basep[wb + 6] = __uint_as_float(f2tf(x.w));
        }
        float4 g = gp[h4], w = wpp[h4];
        S1 += x.x + x.y + x.z + x.w;
        S2 += x.x * x.x + x.y * x.y + x.z * x.z + x.w * x.w;
        A  += x.x * (g.x * w.x) + x.y * (g.y * w.y)
            + x.z * (g.z * w.z) + x.w * (g.w * w.w);
        #pragma unroll
        for (int k = 0; k < HOP; k++) {
            float4 pv = s_pos[k * H4 + h4];
            D[k] += x.x * pv.x + x.y * pv.y + x.z * pv.z + x.w * pv.w;
        }
    }
    #pragma unroll
    for (int s = 16; s; s >>= 1) {
        S1 += __shfl_xor_sync(0xffffffffu, S1, s);
        S2 += __shfl_xor_sync(0xffffffffu, S2, s);
        A  += __shfl_xor_sync(0xffffffffu, A,  s);
        #pragma unroll
        for (int k = 0; k < HOP; k++)
            D[k] += __shfl_xor_sync(0xffffffffu, D[k], s);
    }

    if (lane == 0) {
        float sgw = g_kc[36], bw = g_kc[37], bpv = bp[0];
        float hp = 0.0f, rem = 0.0f, nup = 0.0f;
        float uw[HOP];
        #pragma unroll
        for (int k = 0; k < HOP; k++) {
            float mu  = (S1 + g_kc[k]) * (1.0f / Hv);
            float e2  = (S2 + 2.0f * D[k] + g_kc[12 + k]) * (1.0f / Hv);
            float var = e2 - mu * mu;
            float inv = 1.0f / sqrtf(var + LN_EPS);
            float logit = inv * (A + g_kc[24 + k] - mu * sgw) + bw + bpv;
            float p = 1.0f / (1.0f + expf(-logit));
            float sr = (hp < 1.0f) ? 1.0f : 0.0f;
            float acc = hp + p * sr;
            float nh  = (acc > THRESH)  ? sr : 0.0f;
            sr        = (acc <= THRESH) ? sr : 0.0f;
            hp  += p * sr;
            rem += nh * (1.0f - hp);
            hp  += nh * rem;
            nup += sr + nh;
            uw[k] = p * sr + nh * rem;
        }
        float suf = 1.0f, alpha = 0.0f;
        #pragma unroll
        for (int k = HOP - 1; k >= 0; k--) {
            float gk = uw[k] * suf;
            g_gamma[m * HOP + k] = gk;
            alpha += gk;
            suf *= (1.0f - uw[k]);
        }
        g_alpha[m] = alpha;
        out[(size_t)Mv * Hv + m]      = rem;
        out[(size_t)Mv * Hv + Mv + m] = nup;
    }
}

// =====================================================================
// K3: round Wt -> g_wtr AND compute c_k[o] (exact fp32).
// One block per o-row (1024 blocks x 256 threads).
// =====================================================================
__global__ void k_wt(const float* __restrict__ Wt,
                     const float* __restrict__ pos,
                     const float* __restrict__ bt) {
    int o = blockIdx.x, tid = threadIdx.x;
    int warp = tid >> 5, lane = tid & 31;

    float4 v = ((const float4*)(Wt + (size_t)o * Hv))[tid];
    float4 r;
    r.x = __uint_as_float(f2tf(v.x));
    r.y = __uint_as_float(f2tf(v.y));
    r.z = __uint_as_float(f2tf(v.z));
    r.w = __uint_as_float(f2tf(v.w));
    ((float4*)(g_wtr + (size_t)o * Hv))[tid] = r;

    float d[HOP];
    #pragma unroll
    for (int k = 0; k < HOP; k++) {
        float4 p = ((const float4*)(pos + k * Hv))[tid];
        d[k] = v.x * p.x + v.y * p.y + v.z * p.z + v.w * p.w;
    }
    #pragma unroll
    for (int s = 16; s; s >>= 1)
        #pragma unroll
        for (int k = 0; k < HOP; k++)
            d[k] += __shfl_xor_sync(0xffffffffu, d[k], s);

    __shared__ float red[HOP][8];
    if (lane == 0)
        #pragma unroll
        for (int k = 0; k < HOP; k++) red[k][warp] = d[k];
    __syncthreads();
    if (tid < HOP) {
        float s = 0.0f;
        #pragma unroll
        for (int w = 0; w < 8; w++) s += red[tid][w];
        g_c[tid * Hv + o] = s + bt[o];
    }
}

// =====================================================================
// K4: TF32 mma.sync GEMM, 4-stage cp.async pipeline + epilogue.
//   out[tok][o] = alpha[tok]*(base.Wt^T) + sum_k gamma[tok][k]*c_k[o]
// BM=128 tokens, BN=128 o, BK=16; 8 warps (2M x 4N), warp 64x32.
// A fragment = one LDS.128 (uint4 interleave); B fragment = one LDS.64.
// k-permutation (frag col tig <-> phys 2kp,2kp+1) identical on A and B.
// =====================================================================
#define BMT 128
#define BNO 128
#define KTILES 64
#define AS_STRIDE 66          // uint4 per kp-row (64 + pad 2) -> 8 mod 32 words
#define BS_STRIDE 96          // bytes per n-row (64 + pad 32) -> 24 mod 32 words
#define AS_BYTES (8*AS_STRIDE*16)   // 8448
#define STG_BYTES (AS_BYTES + 128*BS_STRIDE)  // 8448+12288 = 20736
#define RING_BYTES (4*STG_BYTES)    // 82944

__global__ void __launch_bounds__(256, 2) k_gemm(float* __restrict__ out) {
    extern __shared__ char ring[];
    __shared__ float sC[HOP][BNO];
    __shared__ float sG[BMT * HOP];
    __shared__ float sAl[BMT];

    int tid  = threadIdx.x;
    int lane = tid & 31, wid = tid >> 5;
    int tig  = lane & 3, lrow = lane >> 2;
    int warp_m = wid & 1, warp_n = wid >> 1;
    int n0 = blockIdx.x * BNO;            // o offset
    int m0 = blockIdx.y * BMT;            // token offset
    int j0 = m0 >> 1;                     // token-pair offset

    // ---- epilogue data into smem ----
    for (int i = tid; i < HOP * (BNO / 4); i += 256) {
        int k = i >> 5, c4 = i & 31;
        ((float4*)&sC[k][0])[c4] = ((const float4*)&g_c[k * Hv + n0])[c4];
    }
    for (int i = tid; i < BMT * HOP / 4; i += 256)
        ((float4*)sG)[i] = ((const float4*)&g_gamma[(size_t)m0 * HOP])[i];
    if (tid < BMT) sAl[tid] = g_alpha[m0 + tid];

    uint32_t rb = smem_u32(ring);

    auto issue = [&](int kt) {
        uint32_t as = rb + (kt & 3) * STG_BYTES;
        uint32_t bs = as + AS_BYTES;
        #pragma unroll
        for (int i = 0; i < 2; i++) {
            int q = tid + 256 * i;
            int j = q >> 3, kp = q & 7;
            cpasync16(as + (kp * AS_STRIDE + j) * 16,
                      g_basep + ((size_t)(j0 + j) * 512 + kt * 8 + kp) * 4);
        }
        #pragma unroll
        for (int i = 0; i < 2; i++) {
            int q = tid + 256 * i;
            int n = q >> 2, c = q & 3;
            cpasync16(bs + n * BS_STRIDE + c * 16,
                      g_wtr + (size_t)(n0 + n) * Hv + kt * 16 + c * 4);
        }
        CP_COMMIT();
    };

    issue(0); issue(1); issue(2);

    float acc[4][4][4];
    #pragma unroll
    for (int i = 0; i < 4; i++)
        #pragma unroll
        for (int j = 0; j < 4; j++)
            #pragma unroll
            for (int r = 0; r < 4; r++) acc[i][j][r] = 0.0f;

    for (int kt = 0; kt < KTILES; kt++) {
        if (kt + 3 < KTILES) issue(kt + 3);
        if      (kt < KTILES - 3)  CP_WAIT(3);
        else if (kt == KTILES - 3) CP_WAIT(2);
        else if (kt == KTILES - 2) CP_WAIT(1);
        else                       CP_WAIT(0);
        __syncthreads();

        char* as = ring + (kt & 3) * STG_BYTES;
        char* bs = as + AS_BYTES;

        #pragma unroll
        for (int s = 0; s < 2; s++) {
            int kp = s * 4 + tig;
            uint4 af[4];
            #pragma unroll
            for (int i = 0; i < 4; i++)
                af[i] = *(const uint4*)(as + (kp * AS_STRIDE + (warp_m * 4 + i) * 8 + lrow) * 16);
            uint2 bf[4];
            #pragma unroll
            for (int j = 0; j < 4; j++)
                bf[j] = *(const uint2*)(bs + (warp_n * 32 + j * 8 + lrow) * BS_STRIDE + kp * 8);
            #pragma unroll
            for (int i = 0; i < 4; i++)
                #pragma unroll
                for (int j = 0; j < 4; j++)
                    mma_tf32(acc[i][j], af[i].x, af[i].y, af[i].z, af[i].w,
                             bf[j].x, bf[j].y);
        }
        __syncthreads();
    }

    // ---- epilogue ----
    // frag row lrow   -> token-local (warp_m*4+i)*16 + 2*lrow
    // frag row lrow+8 -> +1
    #pragma unroll
    for (int i = 0; i < 4; i++) {
        #pragma unroll
        for (int h = 0; h < 2; h++) {
            int tl = (warp_m * 4 + i) * 16 + 2 * lrow + h;
            float al = sAl[tl];
            const float* grow = &sG[tl * HOP];
            #pragma unroll
            for (int j = 0; j < 4; j++) {
                int cb = warp_n * 32 + j * 8 + 2 * tig;
                float ex = 0.0f, ey = 0.0f;
                #pragma unroll
                for (int k = 0; k < HOP; k++) {
                    float gk = grow[k];
                    float2 cp = *(const float2*)&sC[k][cb];
                    ex += gk * cp.x;
                    ey += gk * cp.y;
                }
                float2 o;
                o.x = al * acc[i][j][2 * h + 0] + ex;
                o.y = al * acc[i][j][2 * h + 1] + ey;
                *(float2*)&out[(size_t)(m0 + tl) * Hv + n0 + cb] = o;
            }
        }
    }
}

// =====================================================================
extern "C" void kernel_launch(void* const* d_in, const int* in_sizes, int n_in,
                              void* d_out, int out_size) {
    const float* inputs  = (const float*)d_in[0];   // [8,2048,1024]
    const float* time_e  = (const float*)d_in[1];   // [1,2048,1024]
    const float* pos_e   = (const float*)d_in[2];   // [1,12,1024]
    const float* ln_g    = (const float*)d_in[3];   // [1024]
    const float* ln_b    = (const float*)d_in[4];   // [1024]
    const float* w_p     = (const float*)d_in[5];   // [1024]
    const float* b_p     = (const float*)d_in[6];   // [1]
    const float* Wt      = (const float*)d_in[7];   // [1024,1024]
    const float* bt      = (const float*)d_in[8];   // [1024]
    float* out = (float*)d_out;

    cudaFuncSetAttribute(k_gemm, cudaFuncAttributeMaxDynamicSharedMemorySize,
                         RING_BYTES);

    k_scal<<<1, 256>>>(pos_e, ln_g, ln_b, w_p);
    k_token<<<Mv / 8, 256>>>(inputs, time_e, pos_e, ln_g, w_p, b_p, out);
    k_wt<<<Hv, 256>>>(Wt, pos_e, bt);
    k_gemm<<<dim3(Hv / BNO, Mv / BMT), 256, RING_BYTES>>>(out);
}